// round 7
// baseline (speedup 1.0000x reference)
#include <cuda_runtime.h>

typedef unsigned long long ull;

#define B_   4
#define C_   64
#define H_   96
#define W_   96
#define DD   8
#define HW   (H_*W_)          // 9216
#define HWD  (H_*W_*DD)       // 73728
#define NIDX 243

#define PX   32
#define PT   8
#define CCH  8
#define NST  72      // 9 i-shifts * 8 channel chunks
#define F1COL 36     // stride/4 odd -> perfect 4-phase LDS.128
#define F2COL 44
#define F1W  (CCH*8*F1COL)     // 2304 words
#define F2W  (CCH*10*F2COL)    // 3520 words
#define SMEM_WORDS (2*F1W + 2*F2W)
#define SMEM_BYTES (SMEM_WORDS*4)   // 46592 B -> 4 blocks/SM

__device__ float g_m1[B_*HW];
__device__ float g_m2[B_*HW];

__device__ __forceinline__ void fma2(ull &d, ull a, ull b) {
    asm("fma.rn.f32x2 %0, %1, %2, %0;" : "+l"(d) : "l"(a), "l"(b));
}
__device__ __forceinline__ ull mul2(ull a, ull b) {
    ull d; asm("mul.rn.f32x2 %0, %1, %2;" : "=l"(d) : "l"(a), "l"(b)); return d;
}
__device__ __forceinline__ ull pack2(float lo, float hi) {
    ull r; asm("mov.b64 %0, {%1, %2};" : "=l"(r) : "f"(lo), "f"(hi)); return r;
}
__device__ __forceinline__ void unpack2(ull v, float &lo, float &hi) {
    asm("mov.b64 {%0, %1}, %2;" : "=f"(lo), "=f"(hi) : "l"(v));
}

// ---------------------------------------------------------------------------
// 4 channels of correlation, MOV-minimized:
//  - even j: pixel pairs (0,1)(2,3)(4,5)(6,7), t-operand e[xp+j/2] (aligned)
//  - odd  j: pixel pairs (1,2)(3,4)(5,6), t-operand e[xq+(j+1)/2] (aligned!)
//            + scalar FFMA edges for px0 / px7
// Only 3 vo packs + 2 edge extracts per channel; e/ve are native ull loads.
// ---------------------------------------------------------------------------
__device__ __forceinline__ void compute4(
    const float* __restrict__ f1s, const float* __restrict__ f2s,
    int clbase, int z, int zi, int lx0,
    ull acc_e[4][5], ull acc_o[3][4], float acc_s0[4], float acc_s7[4])
{
    #pragma unroll
    for (int cu = 0; cu < 4; cu++) {
        const int cl = clbase + cu;
        const ulonglong2* p1 = (const ulonglong2*)(f1s + (cl*8 + z)*F1COL + lx0);
        ulonglong2 V0 = p1[0], V1 = p1[1];
        ull ve[4]; ve[0]=V0.x; ve[1]=V0.y; ve[2]=V1.x; ve[3]=V1.y;

        const ulonglong2* p2 = (const ulonglong2*)(f2s + (cl*10 + zi)*F2COL + lx0);
        ulonglong2 E0 = p2[0], E1 = p2[1], E2 = p2[2], E3 = p2[3];
        ull e[8];
        e[0]=E0.x; e[1]=E0.y; e[2]=E1.x; e[3]=E1.y;
        e[4]=E2.x; e[5]=E2.y; e[6]=E3.x; e[7]=E3.y;

        float v0,v1,v2,v3,v4,v5,v6,v7;
        unpack2(ve[0], v0, v1); unpack2(ve[1], v2, v3);
        unpack2(ve[2], v4, v5); unpack2(ve[3], v6, v7);
        ull vo[3];
        vo[0] = pack2(v1, v2); vo[1] = pack2(v3, v4); vo[2] = pack2(v5, v6);

        #pragma unroll
        for (int xp = 0; xp < 4; xp++)
            #pragma unroll
            for (int jj = 0; jj < 5; jj++)
                fma2(acc_e[xp][jj], ve[xp], e[xp + jj]);

        #pragma unroll
        for (int jo = 0; jo < 4; jo++) {
            fma2(acc_o[0][jo], vo[0], e[jo + 1]);
            fma2(acc_o[1][jo], vo[1], e[jo + 2]);
            fma2(acc_o[2][jo], vo[2], e[jo + 3]);
            float tl, th;
            unpack2(e[jo], tl, th);          // t[2jo+1] = hi
            acc_s0[jo] = fmaf(v0, th, acc_s0[jo]);
            unpack2(e[4 + jo], tl, th);      // t[8+2jo] = lo
            acc_s7[jo] = fmaf(v7, tl, acc_s7[jo]);
        }
    }
}

// ---------------------------------------------------------------------------
// Cost + fused mask kernel, register-staged fill pipeline (R6 structure).
// ---------------------------------------------------------------------------
__global__ void __launch_bounds__(96, 4)
cost_kernel(const float* __restrict__ f1g, const float* __restrict__ f2g,
            float* __restrict__ out, float* __restrict__ omask)
{
    extern __shared__ float sm[];
    float* f1b0 = sm;
    float* f1b1 = sm + F1W;
    float* f2b0 = sm + 2*F1W;
    float* f2b1 = sm + 2*F1W + F2W;

    const int tid = threadIdx.x;
    const int txg = tid & 3;
    const int z   = (tid >> 2) & 7;
    const int k   = tid >> 5;
    const int lx0 = txg * PT;
    const int xb  = blockIdx.x * PX;
    const int y   = blockIdx.y;
    const int b   = blockIdx.z;
    const int zi  = z + k;

    // ---- per-thread fill descriptors (hoisted index math)
    int  f2off[7], f2wb[7];
    bool f2ok[7];
    #pragma unroll
    for (int it = 0; it < 7; it++) {
        int idx = tid + it*96;
        int cl  = idx / 84;
        int r   = idx - cl*84;
        int col = r >> 1;
        int q   = r & 1;
        int gx  = xb - 4 + col;
        f2ok[it]  = (gx >= 0) && (gx < W_);
        f2off[it] = cl*HWD + gx*DD + q*4;
        f2wb[it]  = (cl*10 + 1 + q*4)*F2COL + col;
    }
    int  f1off[6], f1wb[6];
    bool f1ok[6];
    #pragma unroll
    for (int it = 0; it < 6; it++) {
        int idx = tid + it*96;
        f1ok[it] = idx < 512;
        int c = idx >> 6, r = idx & 63, col = r >> 1, q = r & 1;
        f1off[it] = c*HWD + col*DD + q*4;
        f1wb[it]  = (c*8 + q*4)*F1COL + col;
    }

    // zero the z-pad planes of both f2 buffers
    for (int n = tid; n < 2*CCH*2*F2COL; n += 96) {
        int p   = n / (CCH*2*F2COL);
        int r   = n - p*(CCH*2*F2COL);
        int cl  = r / (2*F2COL);
        int r2  = r - cl*(2*F2COL);
        int zp  = (r2 >= F2COL) ? 9 : 0;
        int col = (r2 >= F2COL) ? (r2 - F2COL) : r2;
        (p ? f2b1 : f2b0)[(cl*10 + zp)*F2COL + col] = 0.f;
    }

    float m1x[PT];
    {
        const float* m1p = g_m1 + b*HW + y*W_ + xb + lx0;
        float4 a = *(const float4*)(m1p);
        float4 c = *(const float4*)(m1p + 4);
        m1x[0]=a.x; m1x[1]=a.y; m1x[2]=a.z; m1x[3]=a.w;
        m1x[4]=c.x; m1x[5]=c.y; m1x[6]=c.z; m1x[7]=c.w;
    }
    const bool zedge = (zi == 0) || (zi == 9);

    // ---- prologue: fill stage 0 (i=0, cc=0). yr0 = y-4: valid when y>=4.
    {
        const float* s1 = f1g + ((size_t)(b*C_))*HWD + ((size_t)y*W_ + xb)*DD;
        #pragma unroll
        for (int it = 0; it < 6; it++) {
            if (f1ok[it]) {
                float4 v = *(const float4*)(s1 + f1off[it]);
                int wb = f1wb[it];
                f1b0[wb]=v.x; f1b0[wb+F1COL]=v.y; f1b0[wb+2*F1COL]=v.z; f1b0[wb+3*F1COL]=v.w;
            }
        }
        const int  yr0   = y - 4;
        const bool vrow0 = (yr0 >= 0);
        const float* s2 = f2g + ((size_t)(b*C_))*HWD
                          + (size_t)(vrow0 ? yr0 : 0) * (W_*DD);
        #pragma unroll
        for (int it = 0; it < 7; it++) {
            float4 v = make_float4(0.f,0.f,0.f,0.f);
            if (vrow0 && f2ok[it]) v = *(const float4*)(s2 + f2off[it]);
            int wb = f2wb[it];
            f2b0[wb]=v.x; f2b0[wb+F2COL]=v.y; f2b0[wb+2*F2COL]=v.z; f2b0[wb+3*F2COL]=v.w;
        }
    }

    ull   acc_e[4][5];
    ull   acc_o[3][4];
    float acc_s0[4], acc_s7[4];

    for (int s = 0; s < NST; s++) {
        const int par = s & 1;
        __syncthreads();   // buf[par] filled; prior use of buf[par^1] done

        const float* f1s = par ? f1b1 : f1b0;
        const float* f2s = par ? f2b1 : f2b0;
        float* f1d = par ? f1b0 : f1b1;
        float* f2d = par ? f2b0 : f2b1;

        const int i  = s >> 3;
        const int cc = s & 7;

        const int  sn    = s + 1;
        const bool hasn  = sn < NST;
        const int  in_   = sn >> 3;
        const int  ccn   = sn & 7;
        const int  yrn   = y + in_ - 4;
        const bool vrown = hasn && (yrn >= 0) && (yrn < H_);

        // ---- phase 1: LDG f2-next into registers
        float4 Bv[7];
        {
            const float* s2 = f2g + ((size_t)(b*C_ + ccn*CCH))*HWD
                              + (size_t)(vrown ? yrn : 0) * (W_*DD);
            #pragma unroll
            for (int it = 0; it < 7; it++) {
                float4 v = make_float4(0.f,0.f,0.f,0.f);
                if (vrown && f2ok[it]) v = *(const float4*)(s2 + f2off[it]);
                Bv[it] = v;
            }
        }

        if (cc == 0) {
            #pragma unroll
            for (int xp = 0; xp < 4; xp++)
                #pragma unroll
                for (int jj = 0; jj < 5; jj++) acc_e[xp][jj] = 0ull;
            #pragma unroll
            for (int xq = 0; xq < 3; xq++)
                #pragma unroll
                for (int jo = 0; jo < 4; jo++) acc_o[xq][jo] = 0ull;
            #pragma unroll
            for (int jo = 0; jo < 4; jo++) { acc_s0[jo] = 0.f; acc_s7[jo] = 0.f; }
        }

        // ---- phase 2: compute channels 0-3 (covers f2 LDG latency)
        compute4(f1s, f2s, 0, z, zi, lx0, acc_e, acc_o, acc_s0, acc_s7);

        // ---- phase 3: STS f2-next
        if (hasn) {
            #pragma unroll
            for (int it = 0; it < 7; it++) {
                int wb = f2wb[it];
                f2d[wb]=Bv[it].x; f2d[wb+F2COL]=Bv[it].y;
                f2d[wb+2*F2COL]=Bv[it].z; f2d[wb+3*F2COL]=Bv[it].w;
            }
        }

        // ---- phase 4: LDG f1-next into registers
        float4 Av[6];
        {
            const float* s1 = f1g + ((size_t)(b*C_ + ccn*CCH))*HWD
                              + ((size_t)y*W_ + xb)*DD;
            #pragma unroll
            for (int it = 0; it < 6; it++) {
                float4 v = make_float4(0.f,0.f,0.f,0.f);
                if (hasn && f1ok[it]) v = *(const float4*)(s1 + f1off[it]);
                Av[it] = v;
            }
        }

        // ---- phase 5: compute channels 4-7 (covers f1 LDG latency)
        compute4(f1s, f2s, 4, z, zi, lx0, acc_e, acc_o, acc_s0, acc_s7);

        // ---- phase 6: STS f1-next
        if (hasn) {
            #pragma unroll
            for (int it = 0; it < 6; it++) {
                if (f1ok[it]) {
                    int wb = f1wb[it];
                    f1d[wb]=Av[it].x; f1d[wb+F1COL]=Av[it].y;
                    f1d[wb+2*F1COL]=Av[it].z; f1d[wb+3*F1COL]=Av[it].w;
                }
            }
        }

        // ---- outputs at end of each i-group
        if (cc == 7) {
            const float sc  = 1.0f/64.0f;
            const ull   scc = pack2(sc, sc);
            long obase = ((long)(b*NIDX + k*81 + i*9) * HW
                          + (long)y*W_ + xb + lx0) * DD + z;
            // even j = 2jj : pixel pairs (2xp, 2xp+1)
            #pragma unroll
            for (int jj = 0; jj < 5; jj++)
                #pragma unroll
                for (int xp = 0; xp < 4; xp++) {
                    float s0f, s1f; unpack2(mul2(acc_e[xp][jj], scc), s0f, s1f);
                    out[obase + (long)(2*jj)*HWD + (2*xp  )*DD] = s0f;
                    out[obase + (long)(2*jj)*HWD + (2*xp+1)*DD] = s1f;
                }
            // odd j = 2jo+1 : px0 scalar, pairs (2xq+1, 2xq+2), px7 scalar
            #pragma unroll
            for (int jo = 0; jo < 4; jo++) {
                long ojb = obase + (long)(2*jo+1)*HWD;
                out[ojb]          = acc_s0[jo] * sc;
                #pragma unroll
                for (int xq = 0; xq < 3; xq++) {
                    float s0f, s1f; unpack2(mul2(acc_o[xq][jo], scc), s0f, s1f);
                    out[ojb + (2*xq+1)*DD] = s0f;
                    out[ojb + (2*xq+2)*DD] = s1f;
                }
                out[ojb + 7*DD]   = acc_s7[jo] * sc;
            }
            // fused mask output
            const int yr = y + i - 4;
            const bool vrow = (yr >= 0) && (yr < H_);
            float m2w[16];
            #pragma unroll
            for (int n = 0; n < 16; n++) {
                int gxr = xb + lx0 - 4 + n;
                m2w[n] = (vrow && gxr >= 0 && gxr < W_)
                           ? __ldg(g_m2 + b*HW + yr*W_ + gxr) : 1.0f;
            }
            #pragma unroll
            for (int xi = 0; xi < PT; xi++) {
                #pragma unroll
                for (int j = 0; j < 9; j++) {
                    float mv = zedge ? m1x[xi] : (m1x[xi] * m2w[xi + j]);
                    omask[obase + (long)j*HWD + xi*DD] = mv;
                }
            }
        }
    }
}

// ---------------------------------------------------------------------------
__global__ void mask_sum_kernel(const float* __restrict__ a1,
                                const float* __restrict__ a2) {
    int n = blockIdx.x * blockDim.x + threadIdx.x;
    if (n >= B_*HW) return;
    const float4* p1 = (const float4*)(a1 + (size_t)n * DD);
    const float4* p2 = (const float4*)(a2 + (size_t)n * DD);
    float4 u = p1[0], v = p1[1];
    float s1 = u.x+u.y+u.z+u.w + v.x+v.y+v.z+v.w;
    u = p2[0]; v = p2[1];
    float s2 = u.x+u.y+u.z+u.w + v.x+v.y+v.z+v.w;
    g_m1[n] = fminf(fmaxf(s1, 0.f), 1.f);
    g_m2[n] = fminf(fmaxf(s2, 0.f), 1.f);
}

// ---------------------------------------------------------------------------
extern "C" void kernel_launch(void* const* d_in, const int* in_sizes, int n_in,
                              void* d_out, int out_size) {
    const float* f1 = (const float*)d_in[0];
    const float* a1 = (const float*)d_in[1];
    const float* f2 = (const float*)d_in[2];
    const float* a2 = (const float*)d_in[3];
    float* out      = (float*)d_out;
    float* out_mask = out + (long)B_ * NIDX * HWD;

    mask_sum_kernel<<<(B_*HW + 255) / 256, 256>>>(a1, a2);

    dim3 g(W_ / PX, H_, B_);
    cost_kernel<<<g, 96, SMEM_BYTES>>>(f1, f2, out, out_mask);
}

// round 8
// speedup vs baseline: 1.0190x; 1.0190x over previous
#include <cuda_runtime.h>

typedef unsigned long long ull;

#define B_   4
#define C_   64
#define H_   96
#define W_   96
#define DD   8
#define HW   (H_*W_)          // 9216
#define HWD  (H_*W_*DD)       // 73728
#define NIDX 243

#define PX   32
#define PT   8
#define CCH  8
#define NST  72      // 9 i-shifts * 8 channel chunks
#define F1COL 36     // stride/4 odd -> perfect 4-phase LDS.128
#define F2COL 44
#define F1W  (CCH*8*F1COL)     // 2304 words
#define F2W  (CCH*10*F2COL)    // 3520 words
#define SMEM_WORDS (2*F1W + 2*F2W)
#define SMEM_BYTES (SMEM_WORDS*4)   // 46592 B -> 4 blocks/SM

__device__ float g_m1[B_*HW];
__device__ float g_m2[B_*HW];

__device__ __forceinline__ void fma2(ull &d, ull a, ull b) {
    asm("fma.rn.f32x2 %0, %1, %2, %0;" : "+l"(d) : "l"(a), "l"(b));
}
__device__ __forceinline__ ull mul2(ull a, ull b) {
    ull d; asm("mul.rn.f32x2 %0, %1, %2;" : "=l"(d) : "l"(a), "l"(b)); return d;
}
__device__ __forceinline__ ull pack2(float lo, float hi) {
    ull r; asm("mov.b64 %0, {%1, %2};" : "=l"(r) : "f"(lo), "f"(hi)); return r;
}
__device__ __forceinline__ void unpack2(ull v, float &lo, float &hi) {
    asm("mov.b64 {%0, %1}, %2;" : "=f"(lo), "=f"(hi) : "l"(v));
}
__device__ __forceinline__ void stcs(float* p, float v) {
    asm volatile("st.global.cs.f32 [%0], %1;" :: "l"(p), "f"(v));
}

// ---------------------------------------------------------------------------
// 4 channels of correlation (R6 pairing, ull-native loads).
// vp and e pairs come directly from LDS.128 as 64-bit registers (zero MOV);
// only the 7 odd-shift pairs o[] need packing (unpack halves coalescable).
// Per channel: 6 LDS.128, 7 packs, 36 fma.f32x2 (72 MACs).
// ---------------------------------------------------------------------------
__device__ __forceinline__ void compute4(
    const float* __restrict__ f1s, const float* __restrict__ f2s,
    int clbase, int z, int zi, int lx0, ull acc[4][9])
{
    #pragma unroll
    for (int cu = 0; cu < 4; cu++) {
        const int cl = clbase + cu;
        const ulonglong2* p1 = (const ulonglong2*)(f1s + (cl*8 + z)*F1COL + lx0);
        ulonglong2 V0 = p1[0], V1 = p1[1];
        ull vp[4]; vp[0]=V0.x; vp[1]=V0.y; vp[2]=V1.x; vp[3]=V1.y;

        const ulonglong2* p2 = (const ulonglong2*)(f2s + (cl*10 + zi)*F2COL + lx0);
        ulonglong2 E0 = p2[0], E1 = p2[1], E2 = p2[2], E3 = p2[3];
        ull e[8];
        e[0]=E0.x; e[1]=E0.y; e[2]=E1.x; e[3]=E1.y;
        e[4]=E2.x; e[5]=E2.y; e[6]=E3.x; e[7]=E3.y;

        // o[m] = (t[2m+1], t[2m+2]) = (hi(e[m]), lo(e[m+1]))
        ull o[7];
        #pragma unroll
        for (int m = 0; m < 7; m++) {
            float l0, h0, l1, h1;
            unpack2(e[m],   l0, h0);
            unpack2(e[m+1], l1, h1);
            o[m] = pack2(h0, l1);
        }

        #pragma unroll
        for (int xp = 0; xp < 4; xp++) {
            #pragma unroll
            for (int j = 0; j < 9; j++) {
                ull tp = (j & 1) ? o[xp + ((j-1)>>1)] : e[xp + (j>>1)];
                fma2(acc[xp][j], vp[xp], tp);
            }
        }
    }
}

// ---------------------------------------------------------------------------
// Cost + fused mask kernel, register-staged fill pipeline (R6 structure):
//   sync -> LDG f2-next -> compute cl0-3 -> STS f2-next
//        -> LDG f1-next -> compute cl4-7 -> STS f1-next -> (outputs)
// ---------------------------------------------------------------------------
__global__ void __launch_bounds__(96, 4)
cost_kernel(const float* __restrict__ f1g, const float* __restrict__ f2g,
            float* __restrict__ out, float* __restrict__ omask)
{
    extern __shared__ float sm[];
    float* f1b0 = sm;
    float* f1b1 = sm + F1W;
    float* f2b0 = sm + 2*F1W;
    float* f2b1 = sm + 2*F1W + F2W;

    const int tid = threadIdx.x;
    const int txg = tid & 3;
    const int z   = (tid >> 2) & 7;
    const int k   = tid >> 5;
    const int lx0 = txg * PT;
    const int xb  = blockIdx.x * PX;
    const int y   = blockIdx.y;
    const int b   = blockIdx.z;
    const int zi  = z + k;

    // ---- per-thread fill descriptors (hoisted index math)
    int  f2off[7], f2wb[7];
    bool f2ok[7];
    #pragma unroll
    for (int it = 0; it < 7; it++) {
        int idx = tid + it*96;
        int cl  = idx / 84;
        int r   = idx - cl*84;
        int col = r >> 1;
        int q   = r & 1;
        int gx  = xb - 4 + col;
        f2ok[it]  = (gx >= 0) && (gx < W_);
        f2off[it] = cl*HWD + gx*DD + q*4;
        f2wb[it]  = (cl*10 + 1 + q*4)*F2COL + col;
    }
    int  f1off[6], f1wb[6];
    bool f1ok[6];
    #pragma unroll
    for (int it = 0; it < 6; it++) {
        int idx = tid + it*96;
        f1ok[it] = idx < 512;
        int c = idx >> 6, r = idx & 63, col = r >> 1, q = r & 1;
        f1off[it] = c*HWD + col*DD + q*4;
        f1wb[it]  = (c*8 + q*4)*F1COL + col;
    }

    // zero the z-pad planes of both f2 buffers
    for (int n = tid; n < 2*CCH*2*F2COL; n += 96) {
        int p   = n / (CCH*2*F2COL);
        int r   = n - p*(CCH*2*F2COL);
        int cl  = r / (2*F2COL);
        int r2  = r - cl*(2*F2COL);
        int zp  = (r2 >= F2COL) ? 9 : 0;
        int col = (r2 >= F2COL) ? (r2 - F2COL) : r2;
        (p ? f2b1 : f2b0)[(cl*10 + zp)*F2COL + col] = 0.f;
    }

    float m1x[PT];
    {
        const float* m1p = g_m1 + b*HW + y*W_ + xb + lx0;
        float4 a = *(const float4*)(m1p);
        float4 c = *(const float4*)(m1p + 4);
        m1x[0]=a.x; m1x[1]=a.y; m1x[2]=a.z; m1x[3]=a.w;
        m1x[4]=c.x; m1x[5]=c.y; m1x[6]=c.z; m1x[7]=c.w;
    }
    const bool zedge = (zi == 0) || (zi == 9);

    // ---- prologue: fill stage 0 (i=0, cc=0). yr0 = y-4: valid when y>=4.
    {
        const float* s1 = f1g + ((size_t)(b*C_))*HWD + ((size_t)y*W_ + xb)*DD;
        #pragma unroll
        for (int it = 0; it < 6; it++) {
            if (f1ok[it]) {
                float4 v = *(const float4*)(s1 + f1off[it]);
                int wb = f1wb[it];
                f1b0[wb]=v.x; f1b0[wb+F1COL]=v.y; f1b0[wb+2*F1COL]=v.z; f1b0[wb+3*F1COL]=v.w;
            }
        }
        const int  yr0   = y - 4;
        const bool vrow0 = (yr0 >= 0);             // yr0 < H_ always
        const float* s2 = f2g + ((size_t)(b*C_))*HWD
                          + (size_t)(vrow0 ? yr0 : 0) * (W_*DD);
        #pragma unroll
        for (int it = 0; it < 7; it++) {
            float4 v = make_float4(0.f,0.f,0.f,0.f);
            if (vrow0 && f2ok[it]) v = *(const float4*)(s2 + f2off[it]);
            int wb = f2wb[it];
            f2b0[wb]=v.x; f2b0[wb+F2COL]=v.y; f2b0[wb+2*F2COL]=v.z; f2b0[wb+3*F2COL]=v.w;
        }
    }

    ull acc[4][9];

    for (int s = 0; s < NST; s++) {
        const int par = s & 1;
        __syncthreads();   // buf[par] filled; prior use of buf[par^1] done

        const float* f1s = par ? f1b1 : f1b0;
        const float* f2s = par ? f2b1 : f2b0;
        float* f1d = par ? f1b0 : f1b1;
        float* f2d = par ? f2b0 : f2b1;

        const int i  = s >> 3;
        const int cc = s & 7;

        const int  sn    = s + 1;
        const bool hasn  = sn < NST;
        const int  in_   = sn >> 3;
        const int  ccn   = sn & 7;
        const int  yrn   = y + in_ - 4;
        const bool vrown = hasn && (yrn >= 0) && (yrn < H_);

        // ---- phase 1: LDG f2-next into registers
        float4 Bv[7];
        {
            const float* s2 = f2g + ((size_t)(b*C_ + ccn*CCH))*HWD
                              + (size_t)(vrown ? yrn : 0) * (W_*DD);
            #pragma unroll
            for (int it = 0; it < 7; it++) {
                float4 v = make_float4(0.f,0.f,0.f,0.f);
                if (vrown && f2ok[it]) v = *(const float4*)(s2 + f2off[it]);
                Bv[it] = v;
            }
        }

        if (cc == 0) {
            #pragma unroll
            for (int xp = 0; xp < 4; xp++)
                #pragma unroll
                for (int j = 0; j < 9; j++) acc[xp][j] = 0ull;
        }

        // ---- phase 2: compute channels 0-3 (covers f2 LDG latency)
        compute4(f1s, f2s, 0, z, zi, lx0, acc);

        // ---- phase 3: STS f2-next
        if (hasn) {
            #pragma unroll
            for (int it = 0; it < 7; it++) {
                int wb = f2wb[it];
                f2d[wb]=Bv[it].x; f2d[wb+F2COL]=Bv[it].y;
                f2d[wb+2*F2COL]=Bv[it].z; f2d[wb+3*F2COL]=Bv[it].w;
            }
        }

        // ---- phase 4: LDG f1-next into registers
        float4 Av[6];
        {
            const float* s1 = f1g + ((size_t)(b*C_ + ccn*CCH))*HWD
                              + ((size_t)y*W_ + xb)*DD;
            #pragma unroll
            for (int it = 0; it < 6; it++) {
                float4 v = make_float4(0.f,0.f,0.f,0.f);
                if (hasn && f1ok[it]) v = *(const float4*)(s1 + f1off[it]);
                Av[it] = v;
            }
        }

        // ---- phase 5: compute channels 4-7 (covers f1 LDG latency)
        compute4(f1s, f2s, 4, z, zi, lx0, acc);

        // ---- phase 6: STS f1-next
        if (hasn) {
            #pragma unroll
            for (int it = 0; it < 6; it++) {
                if (f1ok[it]) {
                    int wb = f1wb[it];
                    f1d[wb]=Av[it].x; f1d[wb+F1COL]=Av[it].y;
                    f1d[wb+2*F1COL]=Av[it].z; f1d[wb+3*F1COL]=Av[it].w;
                }
            }
        }

        // ---- outputs at end of each i-group (streaming stores)
        if (cc == 7) {
            const ull scc = pack2(1.0f/64.0f, 1.0f/64.0f);
            long obase = ((long)(b*NIDX + k*81 + i*9) * HW
                          + (long)y*W_ + xb + lx0) * DD + z;
            #pragma unroll
            for (int xp = 0; xp < 4; xp++) {
                #pragma unroll
                for (int j = 0; j < 9; j++) {
                    float s0f, s1f; unpack2(mul2(acc[xp][j], scc), s0f, s1f);
                    stcs(&out[obase + (long)j*HWD + (2*xp  )*DD], s0f);
                    stcs(&out[obase + (long)j*HWD + (2*xp+1)*DD], s1f);
                }
            }
            const int yr = y + i - 4;
            const bool vrow = (yr >= 0) && (yr < H_);
            float m2w[16];
            #pragma unroll
            for (int n = 0; n < 16; n++) {
                int gxr = xb + lx0 - 4 + n;
                m2w[n] = (vrow && gxr >= 0 && gxr < W_)
                           ? __ldg(g_m2 + b*HW + yr*W_ + gxr) : 1.0f;
            }
            #pragma unroll
            for (int xi = 0; xi < PT; xi++) {
                #pragma unroll
                for (int j = 0; j < 9; j++) {
                    float mv = zedge ? m1x[xi] : (m1x[xi] * m2w[xi + j]);
                    stcs(&omask[obase + (long)j*HWD + xi*DD], mv);
                }
            }
        }
    }
}

// ---------------------------------------------------------------------------
__global__ void mask_sum_kernel(const float* __restrict__ a1,
                                const float* __restrict__ a2) {
    int n = blockIdx.x * blockDim.x + threadIdx.x;
    if (n >= B_*HW) return;
    const float4* p1 = (const float4*)(a1 + (size_t)n * DD);
    const float4* p2 = (const float4*)(a2 + (size_t)n * DD);
    float4 u = p1[0], v = p1[1];
    float s1 = u.x+u.y+u.z+u.w + v.x+v.y+v.z+v.w;
    u = p2[0]; v = p2[1];
    float s2 = u.x+u.y+u.z+u.w + v.x+v.y+v.z+v.w;
    g_m1[n] = fminf(fmaxf(s1, 0.f), 1.f);
    g_m2[n] = fminf(fmaxf(s2, 0.f), 1.f);
}

// ---------------------------------------------------------------------------
extern "C" void kernel_launch(void* const* d_in, const int* in_sizes, int n_in,
                              void* d_out, int out_size) {
    const float* f1 = (const float*)d_in[0];
    const float* a1 = (const float*)d_in[1];
    const float* f2 = (const float*)d_in[2];
    const float* a2 = (const float*)d_in[3];
    float* out      = (float*)d_out;
    float* out_mask = out + (long)B_ * NIDX * HWD;

    mask_sum_kernel<<<(B_*HW + 255) / 256, 256>>>(a1, a2);

    dim3 g(W_ / PX, H_, B_);
    cost_kernel<<<g, 96, SMEM_BYTES>>>(f1, f2, out, out_mask);
}